// round 12
// baseline (speedup 1.0000x reference)
#include <cuda_runtime.h>
#include <stdint.h>
#include <math.h>

#define BSZ 2
#define SEQ 2048
#define EMB 768
#define NH  12
#define HD  64
#define BH  (BSZ*NH)     /* 24  */
#define MTOK (BSZ*SEQ)   /* 4096 */

// ---------------------------------------------------------------------------
// Scratch
// ---------------------------------------------------------------------------
__device__ float g_Q[BH * SEQ * HD];
__device__ float g_K[BH * SEQ * HD];
__device__ float g_V[BH * SEQ * HD];
__device__ float g_O[MTOK * EMB];          // attention out, tf32-rounded
__device__ float g_X[MTOK * EMB];          // tf32-rounded hidden states
__device__ float g_W4[4 * EMB * EMB];      // tf32-rounded Wq,Wk,Wv,Wo
__device__ int   g_mask_nz;

// ---------------------------------------------------------------------------
// Mask scan
// ---------------------------------------------------------------------------
__global__ void reset_flag_kernel() { g_mask_nz = 0; }

__global__ void scan_mask_kernel(const float* __restrict__ mask, int n4) {
    int i = blockIdx.x * blockDim.x + threadIdx.x;
    int stride = gridDim.x * blockDim.x;
    int nz = 0;
    for (; i < n4; i += stride) {
        float4 v = ((const float4*)mask)[i];
        nz |= (v.x != 0.f) | (v.y != 0.f) | (v.z != 0.f) | (v.w != 0.f);
    }
    if (__syncthreads_or(nz)) {
        if (threadIdx.x == 0) atomicOr(&g_mask_nz, 1);
    }
}

// ---------------------------------------------------------------------------
// tf32 / cp.async helpers
// ---------------------------------------------------------------------------
__device__ __forceinline__ unsigned cvt_tf32(float x) {
    unsigned r;
    asm("cvt.rna.tf32.f32 %0, %1;" : "=r"(r) : "f"(x));
    return r;
}
__device__ __forceinline__ float cvt_tf32_f(float x) {
    return __uint_as_float(cvt_tf32(x));
}

__device__ __forceinline__ void mma_tf32(float c[4], const unsigned a[4],
                                         unsigned b0, unsigned b1) {
    asm("mma.sync.aligned.m16n8k8.row.col.f32.tf32.tf32.f32 "
        "{%0,%1,%2,%3},{%4,%5,%6,%7},{%8,%9},{%0,%1,%2,%3};"
        : "+f"(c[0]), "+f"(c[1]), "+f"(c[2]), "+f"(c[3])
        : "r"(a[0]), "r"(a[1]), "r"(a[2]), "r"(a[3]), "r"(b0), "r"(b1));
}

__device__ __forceinline__ void cp_async16(unsigned saddr, const void* gptr) {
    asm volatile("cp.async.cg.shared.global [%0], [%1], 16;"
                 :: "r"(saddr), "l"(gptr));
}
__device__ __forceinline__ void cp_commit() {
    asm volatile("cp.async.commit_group;");
}
template <int N>
__device__ __forceinline__ void cp_wait() {
    asm volatile("cp.async.wait_group %0;" :: "n"(N));
}

// ---------------------------------------------------------------------------
// Pre-round pass: X and the 4 weight matrices -> tf32 (rna), into scratch.
// ---------------------------------------------------------------------------
__global__ void round_inputs_kernel(
    const float* __restrict__ X,
    const float* __restrict__ Wq, const float* __restrict__ Wk,
    const float* __restrict__ Wv, const float* __restrict__ Wo)
{
    int i = blockIdx.x * blockDim.x + threadIdx.x;
    int stride = gridDim.x * blockDim.x;
    const int NX = MTOK * EMB / 4;
    const int NW = EMB * EMB / 4;
    for (int k = i; k < NX; k += stride) {
        float4 v = ((const float4*)X)[k];
        v.x = cvt_tf32_f(v.x); v.y = cvt_tf32_f(v.y);
        v.z = cvt_tf32_f(v.z); v.w = cvt_tf32_f(v.w);
        ((float4*)g_X)[k] = v;
    }
    const float* Ws[4] = {Wq, Wk, Wv, Wo};
#pragma unroll
    for (int s = 0; s < 4; s++) {
        float4* dst = (float4*)(g_W4 + (size_t)s * EMB * EMB);
        const float4* src = (const float4*)Ws[s];
        for (int k = i; k < NW; k += stride) {
            float4 v = src[k];
            v.x = cvt_tf32_f(v.x); v.y = cvt_tf32_f(v.y);
            v.z = cvt_tf32_f(v.z); v.w = cvt_tf32_f(v.w);
            dst[k] = v;
        }
    }
}

// ---------------------------------------------------------------------------
// Pipelined tf32 GEMM core v3: CTA tile 128x256, warp tile 64x64 (im=4).
// 256 threads = 8 warps (2m x 4n). BK=32, 2-stage cp.async, two syncs/iter.
// Per warp-iter: 128 mma vs 128 LDS.32 (LDS/mma = 1.0).
// Bank: (row*36 + 8t + m) % 32 = 4g + m -> conflict-free for A and B frags.
// Accumulation order per output element identical to v2 -> bit-same numerics.
// ---------------------------------------------------------------------------
#define DSW 36
#define AST (128 * DSW)                 /* A floats per stage */
#define BST (256 * DSW)                 /* B floats per stage */
#define STG_F (AST + BST)
#define GEMM_SMEM (2 * STG_F * 4)       /* 110592 bytes */

struct GemmAcc { float a[4][8][4]; };

__device__ __forceinline__ void gemm_pipe_core(
    const float* __restrict__ A, const float* __restrict__ W,
    int bm, int bn, GemmAcc& acc, float* sm)
{
    int tid = threadIdx.x;
    int lane = tid & 31;
    int wid = tid >> 5;
    int g = lane >> 2, m = lane & 3;
    int wm = wid & 1, wn = wid >> 1;

#pragma unroll
    for (int im = 0; im < 4; im++)
#pragma unroll
        for (int jn = 0; jn < 8; jn++)
#pragma unroll
            for (int i = 0; i < 4; i++) acc.a[im][jn][i] = 0.f;

    unsigned sbase = (unsigned)__cvta_generic_to_shared(sm);
    // A: 128 rows, 2 threads/row (16-float halves). B: 256 rows, 1 thread/row.
    int rowA = tid >> 1;
    int colA = (tid & 1) * 16;
    const float* agp = A + (size_t)(bm + rowA) * EMB + colA;
    const float* bgp = W + (size_t)(bn + tid) * EMB;
    unsigned soffA = (unsigned)(rowA * DSW + colA) * 4;
    unsigned soffB = (unsigned)(tid * DSW) * 4;

    auto issue = [&](int it) {
        unsigned base = sbase + (unsigned)(it & 1) * (STG_F * 4);
        unsigned bsB  = base + AST * 4;
        int k0 = it * 32;
#pragma unroll
        for (int u = 0; u < 4; u++)
            cp_async16(base + soffA + u * 16, agp + k0 + u * 4);
#pragma unroll
        for (int u = 0; u < 8; u++)
            cp_async16(bsB + soffB + u * 16, bgp + k0 + u * 4);
        cp_commit();
    };

    const int NIT = EMB / 32;   // 24
    issue(0);

    for (int it = 0; it < NIT; it++) {
        if (it + 1 < NIT) { issue(it + 1); cp_wait<1>(); }
        else              { cp_wait<0>(); }
        __syncthreads();

        const float* As = sm + (it & 1) * STG_F;
        const float* Bs = As + AST;

#pragma unroll
        for (int t = 0; t < 4; t++) {
            unsigned af[4][4];
#pragma unroll
            for (int im = 0; im < 4; im++) {
                const float* ab = As + (wm * 64 + im * 16 + g) * DSW + 8 * t + m;
                af[im][0] = __float_as_uint(ab[0]);
                af[im][2] = __float_as_uint(ab[4]);
                af[im][1] = __float_as_uint(ab[8 * DSW]);
                af[im][3] = __float_as_uint(ab[8 * DSW + 4]);
            }
#pragma unroll
            for (int jn = 0; jn < 8; jn++) {
                const float* bb = Bs + (wn * 64 + jn * 8 + g) * DSW + 8 * t + m;
                unsigned b0 = __float_as_uint(bb[0]);
                unsigned b1 = __float_as_uint(bb[4]);
#pragma unroll
                for (int im = 0; im < 4; im++)
                    mma_tf32(acc.a[im][jn], af[im], b0, b1);
            }
        }
        __syncthreads();
    }
}

// ---------------------------------------------------------------------------
// QKV projection: grid (9, 32): x = seg*3 + nb. Writes [bh][s][d] tf32-rounded.
// ---------------------------------------------------------------------------
__global__ void __launch_bounds__(256) qkv_gemm_pipe_kernel(
    const float* __restrict__ bq, const float* __restrict__ bk,
    const float* __restrict__ bv)
{
    extern __shared__ __align__(16) float sm[];

    int seg = blockIdx.x / 3;
    int nb  = blockIdx.x % 3;
    int bm  = blockIdx.y * 128;

    const float* W    = g_W4 + (size_t)seg * EMB * EMB;
    const float* bias = (seg == 0) ? bq : (seg == 1) ? bk : bv;
    float*       out  = (seg == 0) ? g_Q : (seg == 1) ? g_K : g_V;
    const float scale = (seg == 0) ? 0.125f : 1.0f;

    GemmAcc acc;
    gemm_pipe_core(g_X, W, bm, nb * 256, acc, sm);

    int lane = threadIdx.x & 31;
    int wid  = threadIdx.x >> 5;
    int g = lane >> 2, m = lane & 3;
    int wm = wid & 1, wn = wid >> 1;

#pragma unroll
    for (int im = 0; im < 4; im++) {
        int r0 = bm + wm * 64 + im * 16 + g;
        int b = r0 >> 11, s0 = r0 & 2047;
#pragma unroll
        for (int jn = 0; jn < 8; jn++) {
            int nloc = nb * 256 + wn * 64 + jn * 8 + 2 * m;
            int h = nloc >> 6, d = nloc & 63;
            float b0v = bias[nloc], b1v = bias[nloc + 1];
            float* o0 = out + ((size_t)((b * NH + h) * SEQ + s0)) * HD + d;
            float* o1 = o0 + (size_t)8 * HD;
            *(float2*)o0 = make_float2(cvt_tf32_f((acc.a[im][jn][0] + b0v) * scale),
                                       cvt_tf32_f((acc.a[im][jn][1] + b1v) * scale));
            *(float2*)o1 = make_float2(cvt_tf32_f((acc.a[im][jn][2] + b0v) * scale),
                                       cvt_tf32_f((acc.a[im][jn][3] + b1v) * scale));
        }
    }
}

// ---------------------------------------------------------------------------
// Output projection: grid (3, 32). d_out = g_O @ Wo^T + bo (fp32 out).
// ---------------------------------------------------------------------------
__global__ void __launch_bounds__(256) oproj_gemm_pipe_kernel(
    const float* __restrict__ bias, float* __restrict__ C)
{
    extern __shared__ __align__(16) float sm[];

    int bn = blockIdx.x * 256;
    int bm = blockIdx.y * 128;

    GemmAcc acc;
    gemm_pipe_core(g_O, g_W4 + (size_t)3 * EMB * EMB, bm, bn, acc, sm);

    int lane = threadIdx.x & 31;
    int wid  = threadIdx.x >> 5;
    int g = lane >> 2, m = lane & 3;
    int wm = wid & 1, wn = wid >> 1;

#pragma unroll
    for (int im = 0; im < 4; im++) {
        int r0 = bm + wm * 64 + im * 16 + g;
#pragma unroll
        for (int jn = 0; jn < 8; jn++) {
            int n = bn + wn * 64 + jn * 8 + 2 * m;
            float b0v = bias[n], b1v = bias[n + 1];
            float* o0 = C + (size_t)r0 * EMB + n;
            float* o1 = o0 + (size_t)8 * EMB;
            *(float2*)o0 = make_float2(acc.a[im][jn][0] + b0v, acc.a[im][jn][1] + b1v);
            *(float2*)o1 = make_float2(acc.a[im][jn][2] + b0v, acc.a[im][jn][3] + b1v);
        }
    }
}

// ---------------------------------------------------------------------------
// Flash attention v3 (R9, proven ~190us): legacy tf32 mma, shuffle-free PV.
// ---------------------------------------------------------------------------
#define KVS    68
#define TILE_F (64 * KVS)
#define ATT_SMEM (4 * TILE_F * 4)

__global__ void __launch_bounds__(128) attn_tc2_kernel(
    const float* __restrict__ mask,
    const float* __restrict__ attn_bias,
    const float* __restrict__ beta_p,
    const float* __restrict__ bbias_p)
{
    extern __shared__ __align__(16) float sm[];

    int qt   = blockIdx.x;
    int bh   = blockIdx.y;
    int b    = bh / NH;
    int h    = bh % NH;
    int q0   = qt * 128;
    int tid  = threadIdx.x;
    int w    = tid >> 5;
    int lane = tid & 31;
    int g    = lane >> 2;
    int m    = lane & 3;

    const float beta  = beta_p[0];
    const float bbias = bbias_p[0];
    const int masknz  = g_mask_nz;

    const float* Kg    = g_K + (size_t)bh * SEQ * HD;
    const float* Vg    = g_V + (size_t)bh * SEQ * HD;
    const float* biasg = attn_bias + (size_t)bh * SEQ;

    unsigned qf[2][8][4];
    {
        const float* Qb = g_Q + ((size_t)bh * SEQ + q0 + w * 32) * HD;
#pragma unroll
        for (int im = 0; im < 2; im++) {
            const float* r0 = Qb + (size_t)(im * 16 + g) * HD;
            const float* r1 = r0 + 8 * HD;
#pragma unroll
            for (int t = 0; t < 8; t++) {
                qf[im][t][0] = __float_as_uint(r0[8 * t + m]);
                qf[im][t][1] = __float_as_uint(r1[8 * t + m]);
                qf[im][t][2] = __float_as_uint(r0[8 * t + m + 4]);
                qf[im][t][3] = __float_as_uint(r1[8 * t + m + 4]);
            }
        }
    }

    float mr[2][2], lrn[2][2];
    float oa[2][8][4];
#pragma unroll
    for (int im = 0; im < 2; im++) {
        mr[im][0] = -1e30f; mr[im][1] = -1e30f;
        lrn[im][0] = 0.f;   lrn[im][1] = 0.f;
#pragma unroll
        for (int d = 0; d < 8; d++)
#pragma unroll
            for (int i = 0; i < 4; i++) oa[im][d][i] = 0.f;
    }

    unsigned sbase = (unsigned)__cvta_generic_to_shared(sm);
    int lrow = tid >> 4;
    int cir  = tid & 15;

    auto issue_tile = [&](int kt) {
        unsigned kst = sbase + (unsigned)(kt & 1) * (2 * TILE_F * 4);
        unsigned vst = kst + TILE_F * 4;
        const float* kp = Kg + (size_t)(kt * 64) * HD;
        const float* vp = Vg + (size_t)(kt * 64) * HD;
#pragma unroll
        for (int u = 0; u < 8; u++) {
            int row = u * 8 + lrow;
            unsigned soff = (unsigned)(row * KVS + cir * 4) * 4;
            cp_async16(kst + soff, kp + (size_t)row * HD + cir * 4);
            cp_async16(vst + soff, vp + (size_t)row * HD + cir * 4);
        }
        cp_commit();
    };

    issue_tile(0);

    const int NT = SEQ / 64;
    for (int kt = 0; kt < NT; kt++) {
        if (kt + 1 < NT) { issue_tile(kt + 1); cp_wait<1>(); }
        else             { cp_wait<0>(); }
        __syncthreads();

        const float* Ksb = sm + (kt & 1) * 2 * TILE_F;
        const float* Vsb = Ksb + TILE_F;
        int k0 = kt * 64;

        float sc[2][8][4];
#pragma unroll
        for (int im = 0; im < 2; im++)
#pragma unroll
            for (int j = 0; j < 8; j++)
#pragma unroll
                for (int i = 0; i < 4; i++) sc[im][j][i] = 0.f;

#pragma unroll
        for (int t = 0; t < 8; t++) {
#pragma unroll
            for (int j = 0; j < 8; j++) {
                const float* kr = Ksb + (8 * j + g) * KVS + 8 * t + m;
                unsigned b0 = __float_as_uint(kr[0]);
                unsigned b1 = __float_as_uint(kr[4]);
                mma_tf32(sc[0][j], qf[0][t], b0, b1);
                mma_tf32(sc[1][j], qf[1][t], b0, b1);
            }
        }

#pragma unroll
        for (int j = 0; j < 8; j++) {
            float2 bv = *(const float2*)(biasg + k0 + 8 * j + 2 * m);
            float b0v = beta * bv.x + bbias;
            float b1v = beta * bv.y + bbias;
#pragma unroll
            for (int im = 0; im < 2; im++) {
                sc[im][j][0] += b0v; sc[im][j][1] += b1v;
                sc[im][j][2] += b0v; sc[im][j][3] += b1v;
                if (masknz) {
                    int qr = q0 + w * 32 + im * 16 + g;
                    const float* m0p = mask + ((size_t)b * SEQ + qr) * SEQ + k0 + 8 * j + 2 * m;
                    const float* m1p = m0p + (size_t)8 * SEQ;
                    sc[im][j][0] += m0p[0]; sc[im][j][1] += m0p[1];
                    sc[im][j][2] += m1p[0]; sc[im][j][3] += m1p[1];
                }
            }
        }

#pragma unroll
        for (int im = 0; im < 2; im++) {
            float mx0 = sc[im][0][0], mx1 = sc[im][0][2];
#pragma unroll
            for (int j = 0; j < 8; j++) {
                mx0 = fmaxf(mx0, fmaxf(sc[im][j][0], sc[im][j][1]));
                mx1 = fmaxf(mx1, fmaxf(sc[im][j][2], sc[im][j][3]));
            }
            mx0 = fmaxf(mx0, __shfl_xor_sync(0xffffffffu, mx0, 1));
            mx0 = fmaxf(mx0, __shfl_xor_sync(0xffffffffu, mx0, 2));
            mx1 = fmaxf(mx1, __shfl_xor_sync(0xffffffffu, mx1, 1));
            mx1 = fmaxf(mx1, __shfl_xor_sync(0xffffffffu, mx1, 2));

            float mn0 = fmaxf(mr[im][0], mx0);
            float mn1 = fmaxf(mr[im][1], mx1);
            float al0 = __expf(mr[im][0] - mn0);
            float al1 = __expf(mr[im][1] - mn1);

            float s0 = 0.f, s1 = 0.f;
#pragma unroll
            for (int j = 0; j < 8; j++) {
                sc[im][j][0] = __expf(sc[im][j][0] - mn0);
                sc[im][j][1] = __expf(sc[im][j][1] - mn0);
                sc[im][j][2] = __expf(sc[im][j][2] - mn1);
                sc[im][j][3] = __expf(sc[im][j][3] - mn1);
                s0 += sc[im][j][0] + sc[im][j][1];
                s1 += sc[im][j][2] + sc[im][j][3];
            }
            s0 += __shfl_xor_sync(0xffffffffu, s0, 1);
            s0 += __shfl_xor_sync(0xffffffffu, s0, 2);
            s1 += __shfl_xor_sync(0xffffffffu, s1, 1);
            s1 += __shfl_xor_sync(0xffffffffu, s1, 2);

            lrn[im][0] = lrn[im][0] * al0 + s0;
            lrn[im][1] = lrn[im][1] * al1 + s1;
            mr[im][0] = mn0; mr[im][1] = mn1;
#pragma unroll
            for (int d = 0; d < 8; d++) {
                oa[im][d][0] *= al0; oa[im][d][1] *= al0;
                oa[im][d][2] *= al1; oa[im][d][3] *= al1;
            }
        }

#pragma unroll
        for (int j = 0; j < 8; j++) {
            unsigned pa[2][4];
#pragma unroll
            for (int im = 0; im < 2; im++) {
                pa[im][0] = cvt_tf32(sc[im][j][0]);
                pa[im][1] = cvt_tf32(sc[im][j][2]);
                pa[im][2] = cvt_tf32(sc[im][j][1]);
                pa[im][3] = cvt_tf32(sc[im][j][3]);
            }
            const float* vr = Vsb + (8 * j + 2 * m) * KVS + g;
#pragma unroll
            for (int d = 0; d < 8; d++) {
                unsigned b0 = __float_as_uint(vr[8 * d]);
                unsigned b1 = __float_as_uint(vr[KVS + 8 * d]);
                mma_tf32(oa[0][d], pa[0], b0, b1);
                mma_tf32(oa[1][d], pa[1], b0, b1);
            }
        }
        __syncthreads();
    }

#pragma unroll
    for (int im = 0; im < 2; im++) {
        float inv0 = 1.f / lrn[im][0];
        float inv1 = 1.f / lrn[im][1];
        int qr = q0 + w * 32 + im * 16 + g;
        float* O0 = g_O + ((size_t)(b * SEQ + qr)) * EMB + h * HD;
        float* O1 = O0 + (size_t)8 * EMB;
#pragma unroll
        for (int d = 0; d < 8; d++) {
            int c = 8 * d + 2 * m;
            *(float2*)(O0 + c) = make_float2(cvt_tf32_f(oa[im][d][0] * inv0),
                                             cvt_tf32_f(oa[im][d][1] * inv0));
            *(float2*)(O1 + c) = make_float2(cvt_tf32_f(oa[im][d][2] * inv1),
                                             cvt_tf32_f(oa[im][d][3] * inv1));
        }
    }
}

// ---------------------------------------------------------------------------
// Launch
// ---------------------------------------------------------------------------
extern "C" void kernel_launch(void* const* d_in, const int* in_sizes, int n_in,
                              void* d_out, int out_size) {
    const float* X     = (const float*)d_in[0];
    const float* mask  = (const float*)d_in[1];
    const float* abias = (const float*)d_in[2];
    const float* Wq    = (const float*)d_in[3];
    const float* bq    = (const float*)d_in[4];
    const float* Wk    = (const float*)d_in[5];
    const float* bk    = (const float*)d_in[6];
    const float* Wv    = (const float*)d_in[7];
    const float* bv    = (const float*)d_in[8];
    const float* Wo    = (const float*)d_in[9];
    const float* bo    = (const float*)d_in[10];
    const float* beta  = (const float*)d_in[11];
    const float* bbias = (const float*)d_in[12];
    float* out = (float*)d_out;

    cudaFuncSetAttribute(attn_tc2_kernel,
                         cudaFuncAttributeMaxDynamicSharedMemorySize, ATT_SMEM);
    cudaFuncSetAttribute(qkv_gemm_pipe_kernel,
                         cudaFuncAttributeMaxDynamicSharedMemorySize, GEMM_SMEM);
    cudaFuncSetAttribute(oproj_gemm_pipe_kernel,
                         cudaFuncAttributeMaxDynamicSharedMemorySize, GEMM_SMEM);

    reset_flag_kernel<<<1, 32>>>();
    scan_mask_kernel<<<1024, 256>>>(mask, BSZ * SEQ * SEQ / 4);
    round_inputs_kernel<<<512, 256>>>(X, Wq, Wk, Wv, Wo);
    qkv_gemm_pipe_kernel<<<dim3(9, 32), 256, GEMM_SMEM>>>(bq, bk, bv);
    attn_tc2_kernel<<<dim3(SEQ / 128, BH), 128, ATT_SMEM>>>(mask, abias, beta, bbias);
    oproj_gemm_pipe_kernel<<<dim3(3, 32), 256, GEMM_SMEM>>>(bo, out);
}